// round 7
// baseline (speedup 1.0000x reference)
#include <cuda_runtime.h>
#include <cstdint>

// ---------------------------------------------------------------------------
// DistancePredictor: out[b,i,j,n] = relu(xi[b,i,:]*xj[b,j,:]) @ Wo[:,n] + bo[n]
//   xi = x@Wi + bi, xj = x@Wj + bj
// B=2, L=384, D=1280, H=256, NB=10
// ---------------------------------------------------------------------------

#define B_    2
#define L_    384
#define D_    1280
#define H_    256
#define NB_   10
#define ROWS_ 768
#define NTOT_ 512              // concat: cols 0-255 = xi, 256-511 = xj
#define SPLITK_ 10
#define KCH_  128              // D_/SPLITK_

__device__ __align__(16) float g_xij[ROWS_ * NTOT_];
__device__ __align__(16) float g_part[SPLITK_ * ROWS_ * NTOT_];   // 15.7 MB

// ---- packed f32x2 helpers -------------------------------------------------
typedef unsigned long long u64;

__device__ __forceinline__ u64 pk2(float a, float b) {
    u64 r;
    asm("mov.b64 %0, {%1, %2};"
        : "=l"(r) : "r"(__float_as_uint(a)), "r"(__float_as_uint(b)));
    return r;
}
__device__ __forceinline__ void fma2(u64& d, u64 a, u64 b) {
    asm("fma.rn.f32x2 %0, %1, %2, %0;" : "+l"(d) : "l"(a), "l"(b));
}
__device__ __forceinline__ u64 mul2(u64 a, u64 b) {
    u64 d;
    asm("mul.rn.f32x2 %0, %1, %2;" : "=l"(d) : "l"(a), "l"(b));
    return d;
}
// relu on both halves of a packed f32x2 (register-pair aliasing is free; 2 FMNMX)
__device__ __forceinline__ u64 relu2(u64 v) {
    float lo = __uint_as_float((unsigned)v);
    float hi = __uint_as_float((unsigned)(v >> 32));
    return pk2(fmaxf(lo, 0.0f), fmaxf(hi, 0.0f));
}

__device__ __forceinline__ void cp16(uint32_t s, const void* g) {
    asm volatile("cp.async.cg.shared.global [%0], [%1], 16;\n" :: "r"(s), "l"(g));
}
__device__ __forceinline__ void cp_commit() {
    asm volatile("cp.async.commit_group;\n" ::: "memory");
}

// ---------------------------------------------------------------------------
// Stage 1: merged projection GEMM, C[768,512] = X[768,1280] @ [Wi|Wj].
// 128x128 tile, 256 threads, 8x8/thread, BK=16, cp.async 3-stage pipeline.
// grid (4, 6, 10): x = n-tile, y = m-tile, z = split-K.
// ---------------------------------------------------------------------------
__global__ __launch_bounds__(256) void proj_kernel(
    const float* __restrict__ X,
    const float* __restrict__ Wi, const float* __restrict__ Wj)
{
    const int split = blockIdx.z;
    const int n0    = blockIdx.x * 128;
    const float* W  = (blockIdx.x < 2) ? Wi : Wj;
    const int wc0   = n0 & 255;
    const int m0    = blockIdx.y * 128;
    const int kb    = split * KCH_;
    float* P = g_part + (size_t)split * ROWS_ * NTOT_;

    __shared__ __align__(16) float As[3][128 * 16];   // [m][k] row-major
    __shared__ __align__(16) float Bs[3][16 * 128];   // [k][n]

    const int tid = threadIdx.x;
    const int tx  = tid & 15;
    const int ty  = tid >> 4;

    // A loader: thread -> row a_m, two float4 at k-offset a_kf*4, (a_kf+1)*4
    const int a_m  = tid >> 1;
    const int a_kf = (tid & 1) * 2;
    // B loader: rows b_k, b_k+8; 16B along n
    const int b_k  = tid >> 5;
    const int b_n4 = (tid & 31) << 2;

    u64 acc[8][4];
    #pragma unroll
    for (int r = 0; r < 8; r++)
        #pragma unroll
        for (int c = 0; c < 4; c++) acc[r][c] = 0ull;

    auto issue = [&](int c, int s) {
        const float* ga = &X[(size_t)(m0 + a_m) * D_ + kb + c * 16 + a_kf * 4];
        uint32_t sa = (uint32_t)__cvta_generic_to_shared(&As[s][a_m * 16 + a_kf * 4]);
        cp16(sa,      ga);
        cp16(sa + 16, ga + 4);
        const float* gb = &W[(size_t)(kb + c * 16 + b_k) * H_ + wc0 + b_n4];
        uint32_t sb = (uint32_t)__cvta_generic_to_shared(&Bs[s][b_k * 128 + b_n4]);
        cp16(sb,               gb);
        cp16(sb + 8 * 128 * 4, gb + 8 * H_);
        cp_commit();
    };

    issue(0, 0);
    issue(1, 1);

    for (int c = 0; c < 8; c++) {
        if (c < 7) asm volatile("cp.async.wait_group 1;\n" ::: "memory");
        else       asm volatile("cp.async.wait_group 0;\n" ::: "memory");
        __syncthreads();

        const float* A  = As[c % 3];
        const float* Bl = Bs[c % 3];

        #pragma unroll
        for (int kk = 0; kk < 16; kk++) {
            float a[8];
            #pragma unroll
            for (int r = 0; r < 4; r++) {
                a[r]     = A[(ty * 4 + r) * 16 + kk];        // broadcast LDS
                a[r + 4] = A[(ty * 4 + 64 + r) * 16 + kk];
            }
            float4 b0 = *(const float4*)&Bl[kk * 128 + tx * 4];
            float4 b1 = *(const float4*)&Bl[kk * 128 + tx * 4 + 64];
            u64 b2[4] = { pk2(b0.x, b0.y), pk2(b0.z, b0.w),
                          pk2(b1.x, b1.y), pk2(b1.z, b1.w) };
            #pragma unroll
            for (int r = 0; r < 8; r++) {
                u64 ad = pk2(a[r], a[r]);
                #pragma unroll
                for (int cc = 0; cc < 4; cc++) fma2(acc[r][cc], ad, b2[cc]);
            }
        }
        if (c + 2 < 8) issue(c + 2, (c + 2) % 3);
    }

    #pragma unroll
    for (int r = 0; r < 8; r++) {
        int m = m0 + ty * 4 + ((r < 4) ? r : 64 + (r - 4));
        float* dst = &P[(size_t)m * NTOT_ + n0 + tx * 4];
        *(u64*)&dst[0]  = acc[r][0];
        *(u64*)&dst[2]  = acc[r][1];
        *(u64*)&dst[64] = acc[r][2];
        *(u64*)&dst[66] = acc[r][3];
    }
}

// ---------------------------------------------------------------------------
// Stage 1b: sum 10 split-K partials + bias -> g_xij  (grid 384, 256 thr)
// ---------------------------------------------------------------------------
__global__ __launch_bounds__(256) void reduce_kernel(
    const float* __restrict__ bi, const float* __restrict__ bj)
{
    const int q    = blockIdx.x * 256 + threadIdx.x;   // float4 index
    const int flat = q << 2;
    const int col  = flat & (NTOT_ - 1);

    float4 s = *(const float4*)&g_part[flat];
    #pragma unroll
    for (int sp = 1; sp < SPLITK_; sp++) {
        float4 v = *(const float4*)&g_part[(size_t)sp * ROWS_ * NTOT_ + flat];
        s.x += v.x; s.y += v.y; s.z += v.z; s.w += v.w;
    }
    const float* bias = (col < H_) ? (bi + col) : (bj + col - H_);
    float4 bv = *(const float4*)bias;
    s.x += bv.x; s.y += bv.y; s.z += bv.z; s.w += bv.w;

    *(float4*)&g_xij[flat] = s;
}

// ---------------------------------------------------------------------------
// Stage 2: out[b,i,j,:] = relu(xi_i ∘ xj_j) @ Wo + bo
// 512 threads = 16 warps. Block tile 16 i x 128 j. Warp w: i-pair (w&7),
// j-half (w>>3); lane owns one j-pair. Accumulators packed over the j-pair:
// product pair from ONE mul.f32x2, Wo pre-duplicated in smem as u64.
// All smem staged once; ONE barrier. Grid (3,24,2) = 144 blocks.
// ---------------------------------------------------------------------------
#define XJ_STRIDE 130          // 4*130 % 32 == 8 -> conflict-free scatter
#define XI_STRIDE 18

__global__ __launch_bounds__(512) void pair_kernel(
    const float* __restrict__ Wo, const float* __restrict__ bo,
    float* __restrict__ out)
{
    extern __shared__ __align__(16) float sm[];
    float* XjT = sm;                                   // [256][130]
    float* XiT = sm + 256 * XJ_STRIDE;                 // [256][18]
    u64*  WoD  = (u64*)(XiT + 256 * XI_STRIDE);        // [2560] duplicated

    const int tid   = threadIdx.x;
    const int w     = tid >> 5;
    const int lane  = tid & 31;
    const int ip    = w & 7;           // i-pair index (i = 2*ip, 2*ip+1)
    const int jhalf = w >> 3;          // 0 or 1
    const int b     = blockIdx.z;
    const int i0    = blockIdx.y * 16;
    const int j0    = blockIdx.x * 128;

    // ---- stage XjT[h][j] from g_xij cols 256.. (4 threads per j) ----
    {
        const int jl  = tid >> 2;
        const int hof = (tid & 3) << 2;
        const float* src = &g_xij[(size_t)(b * L_ + j0 + jl) * NTOT_ + H_];
        #pragma unroll
        for (int q = 0; q < 16; q++) {
            int h = hof + q * 16;
            float4 v = *(const float4*)&src[h];
            XjT[(h + 0) * XJ_STRIDE + jl] = v.x;
            XjT[(h + 1) * XJ_STRIDE + jl] = v.y;
            XjT[(h + 2) * XJ_STRIDE + jl] = v.z;
            XjT[(h + 3) * XJ_STRIDE + jl] = v.w;
        }
    }
    // ---- stage XiT[h][i] (32 threads per i) ----
    {
        const int il = tid >> 5;                 // 0..15
        const int hb = (tid & 31) << 3;          // 0..248 step 8
        const float* src = &g_xij[(size_t)(b * L_ + i0 + il) * NTOT_];
        #pragma unroll
        for (int p = 0; p < 2; p++) {
            int h = hb + p * 4;
            float4 v = *(const float4*)&src[h];
            XiT[(h + 0) * XI_STRIDE + il] = v.x;
            XiT[(h + 1) * XI_STRIDE + il] = v.y;
            XiT[(h + 2) * XI_STRIDE + il] = v.z;
            XiT[(h + 3) * XI_STRIDE + il] = v.w;
        }
    }
    // ---- stage duplicated Wo ----
    for (int q = tid; q < H_ * NB_; q += 512) {
        float v = Wo[q];
        WoD[q] = pk2(v, v);
    }

    u64 acc[2][NB_];
    #pragma unroll
    for (int i = 0; i < 2; i++)
        #pragma unroll
        for (int c = 0; c < NB_; c++) acc[i][c] = 0ull;

    __syncthreads();    // the ONLY barrier

    const int jb = jhalf * 64 + lane * 2;        // local j-pair base

    #pragma unroll 2
    for (int h = 0; h < H_; h++) {
        float2 xi2 = *(const float2*)&XiT[h * XI_STRIDE + ip * 2];
        u64 xj = *(const u64*)&XjT[h * XJ_STRIDE + jb];   // (xj_ja, xj_jb)

        u64 p0 = relu2(mul2(pk2(xi2.x, xi2.x), xj));
        u64 p1 = relu2(mul2(pk2(xi2.y, xi2.y), xj));

        const ulonglong2* wr = (const ulonglong2*)&WoD[h * NB_];  // 80B, 16B-aligned
        #pragma unroll
        for (int c5 = 0; c5 < 5; c5++) {
            ulonglong2 wv = wr[c5];                // LDS.128 broadcast
            fma2(acc[0][2 * c5 + 0], p0, wv.x);
            fma2(acc[0][2 * c5 + 1], p0, wv.y);
            fma2(acc[1][2 * c5 + 0], p1, wv.x);
            fma2(acc[1][2 * c5 + 1], p1, wv.y);
        }
    }

    // ---- epilogue: unpack j-pair, add bo, store ----
    const int ja = j0 + jb;                      // global j (pair ja, ja+1)
    #pragma unroll
    for (int i = 0; i < 2; i++) {
        const int gi = i0 + ip * 2 + i;
        float* dst = &out[((size_t)(b * L_ + gi) * L_ + ja) * NB_];
        #pragma unroll
        for (int c = 0; c < NB_; c++) {
            float bv = bo[c];
            float lo = __uint_as_float((unsigned)acc[i][c]);
            float hi = __uint_as_float((unsigned)(acc[i][c] >> 32));
            dst[c]       = lo + bv;              // j = ja
            dst[NB_ + c] = hi + bv;              // j = ja+1
        }
    }
}

// ---------------------------------------------------------------------------
extern "C" void kernel_launch(void* const* d_in, const int* in_sizes, int n_in,
                              void* d_out, int out_size)
{
    const float* x  = (const float*)d_in[0];
    const float* Wi = (const float*)d_in[1];
    const float* bi = (const float*)d_in[2];
    const float* Wj = (const float*)d_in[3];
    const float* bj = (const float*)d_in[4];
    const float* Wo = (const float*)d_in[5];
    const float* bo = (const float*)d_in[6];
    float* out = (float*)d_out;

    const int pair_smem =
        (256 * XJ_STRIDE + 256 * XI_STRIDE) * 4 + H_ * NB_ * 8;   // 172,032 B
    cudaFuncSetAttribute(pair_kernel,
                         cudaFuncAttributeMaxDynamicSharedMemorySize, pair_smem);

    proj_kernel<<<dim3(4, 6, SPLITK_), 256>>>(x, Wi, Wj);
    reduce_kernel<<<dim3(384), 256>>>(bi, bj);
    pair_kernel<<<dim3(L_ / 128, L_ / 16, B_), 512, pair_smem>>>(Wo, bo, out);
}

// round 11
// speedup vs baseline: 1.2874x; 1.2874x over previous
#include <cuda_runtime.h>
#include <cuda_bf16.h>
#include <cstdint>

// ---------------------------------------------------------------------------
// DistancePredictor: out[b,i,j,n] = relu(xi[b,i,:]*xj[b,j,:]) @ Wo[:,n] + bo[n]
//   xi = x@Wi + bi, xj = x@Wj + bj
// B=2, L=384, D=1280, H=256, NB=10
// ---------------------------------------------------------------------------

#define B_    2
#define L_    384
#define D_    1280
#define H_    256
#define NB_   10
#define ROWS_ 768
#define NTOT_ 512              // concat: cols 0-255 = xi, 256-511 = xj
#define SPLITK_ 10
#define KCH_  128              // D_/SPLITK_

__device__ __align__(16) float g_xij[ROWS_ * NTOT_];
__device__ __align__(16) float g_part[SPLITK_ * ROWS_ * NTOT_];

typedef unsigned long long u64;
typedef unsigned int       u32;

__device__ __forceinline__ u64 pk2(float a, float b) {
    u64 r;
    asm("mov.b64 %0, {%1, %2};"
        : "=l"(r) : "r"(__float_as_uint(a)), "r"(__float_as_uint(b)));
    return r;
}
__device__ __forceinline__ void fma2(u64& d, u64 a, u64 b) {
    asm("fma.rn.f32x2 %0, %1, %2, %0;" : "+l"(d) : "l"(a), "l"(b));
}
__device__ __forceinline__ u64 mul2(u64 a, u64 b) {
    u64 d;
    asm("mul.rn.f32x2 %0, %1, %2;" : "=l"(d) : "l"(a), "l"(b));
    return d;
}

__device__ __forceinline__ void cp16(u32 s, const void* g) {
    asm volatile("cp.async.cg.shared.global [%0], [%1], 16;\n" :: "r"(s), "l"(g));
}
__device__ __forceinline__ void cp_commit() {
    asm volatile("cp.async.commit_group;\n" ::: "memory");
}

// ---------------------------------------------------------------------------
// Stage 1: merged projection GEMM (unchanged from R7 except occupancy bound)
// ---------------------------------------------------------------------------
__global__ __launch_bounds__(256, 2) void proj_kernel(
    const float* __restrict__ X,
    const float* __restrict__ Wi, const float* __restrict__ Wj)
{
    const int split = blockIdx.z;
    const int n0    = blockIdx.x * 128;
    const float* W  = (blockIdx.x < 2) ? Wi : Wj;
    const int wc0   = n0 & 255;
    const int m0    = blockIdx.y * 128;
    const int kb    = split * KCH_;
    float* P = g_part + (size_t)split * ROWS_ * NTOT_;

    __shared__ __align__(16) float As[3][128 * 16];   // [m][k]
    __shared__ __align__(16) float Bs[3][16 * 128];   // [k][n]

    const int tid = threadIdx.x;
    const int tx  = tid & 15;
    const int ty  = tid >> 4;

    const int a_m  = tid >> 1;
    const int a_kf = (tid & 1) * 2;
    const int b_k  = tid >> 5;
    const int b_n4 = (tid & 31) << 2;

    u64 acc[8][4];
    #pragma unroll
    for (int r = 0; r < 8; r++)
        #pragma unroll
        for (int c = 0; c < 4; c++) acc[r][c] = 0ull;

    auto issue = [&](int c, int s) {
        const float* ga = &X[(size_t)(m0 + a_m) * D_ + kb + c * 16 + a_kf * 4];
        u32 sa = (u32)__cvta_generic_to_shared(&As[s][a_m * 16 + a_kf * 4]);
        cp16(sa,      ga);
        cp16(sa + 16, ga + 4);
        const float* gb = &W[(size_t)(kb + c * 16 + b_k) * H_ + wc0 + b_n4];
        u32 sb = (u32)__cvta_generic_to_shared(&Bs[s][b_k * 128 + b_n4]);
        cp16(sb,               gb);
        cp16(sb + 8 * 128 * 4, gb + 8 * H_);
        cp_commit();
    };

    issue(0, 0);
    issue(1, 1);

    for (int c = 0; c < 8; c++) {
        if (c < 7) asm volatile("cp.async.wait_group 1;\n" ::: "memory");
        else       asm volatile("cp.async.wait_group 0;\n" ::: "memory");
        __syncthreads();

        const float* A  = As[c % 3];
        const float* Bl = Bs[c % 3];

        #pragma unroll
        for (int kk = 0; kk < 16; kk++) {
            float a[8];
            #pragma unroll
            for (int r = 0; r < 4; r++) {
                a[r]     = A[(ty * 4 + r) * 16 + kk];
                a[r + 4] = A[(ty * 4 + 64 + r) * 16 + kk];
            }
            float4 b0 = *(const float4*)&Bl[kk * 128 + tx * 4];
            float4 b1 = *(const float4*)&Bl[kk * 128 + tx * 4 + 64];
            u64 b2[4] = { pk2(b0.x, b0.y), pk2(b0.z, b0.w),
                          pk2(b1.x, b1.y), pk2(b1.z, b1.w) };
            #pragma unroll
            for (int r = 0; r < 8; r++) {
                u64 ad = pk2(a[r], a[r]);
                #pragma unroll
                for (int cc = 0; cc < 4; cc++) fma2(acc[r][cc], ad, b2[cc]);
            }
        }
        if (c + 2 < 8) issue(c + 2, (c + 2) % 3);
    }

    #pragma unroll
    for (int r = 0; r < 8; r++) {
        int m = m0 + ty * 4 + ((r < 4) ? r : 64 + (r - 4));
        float* dst = &P[(size_t)m * NTOT_ + n0 + tx * 4];
        *(u64*)&dst[0]  = acc[r][0];
        *(u64*)&dst[2]  = acc[r][1];
        *(u64*)&dst[64] = acc[r][2];
        *(u64*)&dst[66] = acc[r][3];
    }
}

// ---------------------------------------------------------------------------
// Stage 1b: sum 10 split-K partials + bias -> g_xij
// ---------------------------------------------------------------------------
__global__ __launch_bounds__(256) void reduce_kernel(
    const float* __restrict__ bi, const float* __restrict__ bj)
{
    const int q    = blockIdx.x * 256 + threadIdx.x;
    const int flat = q << 2;
    const int col  = flat & (NTOT_ - 1);

    float4 s = *(const float4*)&g_part[flat];
    #pragma unroll
    for (int sp = 1; sp < SPLITK_; sp++) {
        float4 v = *(const float4*)&g_part[(size_t)sp * ROWS_ * NTOT_ + flat];
        s.x += v.x; s.y += v.y; s.z += v.z; s.w += v.w;
    }
    const float* bias = (col < H_) ? (bi + col) : (bj + col - H_);
    float4 bv = *(const float4*)bias;
    s.x += bv.x; s.y += bv.y; s.z += bv.z; s.w += bv.w;

    *(float4*)&g_xij[flat] = s;
}

// ---------------------------------------------------------------------------
// Stage 2 (TENSORIZED): out[b,i,j,:] = relu(xi_i ∘ xj_j) @ Wo + bo
// via mma.sync.m16n8k16 bf16: A = relu-product tile (16 j-pairs x 16 h, built
// on-the-fly in registers, double-bf16 split Rh+Rl), B = Wo^T (bf16 hi+lo).
// Terms kept: Rh*Wh + Rh*Wl + Rl*Wh  (error ~2^-17 per term).
// Block: 512 thr = 16 warps; warp w owns row i0+w, loops 8 j-chunks of 16.
// Grid (3, 24, 2) = 144 blocks.
// ---------------------------------------------------------------------------
#define XJ_S 260               // float stride: %4==0 (16B stores), 4j%32 banks
#define XI_S 260
#define WO_S 264               // ushort stride: conflict-free u32 B-frag loads

__device__ __forceinline__ void mma16816(float* d, const u32* a, u32 b0, u32 b1) {
    asm volatile(
        "mma.sync.aligned.m16n8k16.row.col.f32.bf16.bf16.f32 "
        "{%0,%1,%2,%3}, {%4,%5,%6,%7}, {%8,%9}, {%0,%1,%2,%3};"
        : "+f"(d[0]), "+f"(d[1]), "+f"(d[2]), "+f"(d[3])
        : "r"(a[0]), "r"(a[1]), "r"(a[2]), "r"(a[3]), "r"(b0), "r"(b1));
}

// product -> relu -> bf16 split (rh = bf16x2 of p, rl = bf16x2 of p - rh)
__device__ __forceinline__ void makeA(u64 xi2, u64 xj2, u32& rh, u32& rl) {
    u64 p = mul2(xi2, xj2);
    float plo = fmaxf(__uint_as_float((u32)p), 0.0f);
    float phi = fmaxf(__uint_as_float((u32)(p >> 32)), 0.0f);
    asm("cvt.rn.bf16x2.f32 %0, %1, %2;" : "=r"(rh) : "f"(phi), "f"(plo));
    float qlo = plo - __uint_as_float(rh << 16);
    float qhi = phi - __uint_as_float(rh & 0xffff0000u);
    asm("cvt.rn.bf16x2.f32 %0, %1, %2;" : "=r"(rl) : "f"(qhi), "f"(qlo));
}

__global__ __launch_bounds__(512) void pair_kernel(
    const float* __restrict__ Wo, const float* __restrict__ bo,
    float* __restrict__ out)
{
    extern __shared__ __align__(16) char smraw[];
    float*          Xj   = (float*)smraw;                          // [128][260]
    float*          Xi   = (float*)(smraw + 128 * XJ_S * 4);       // [16][260]
    unsigned short* WoTh = (unsigned short*)(smraw + 128 * XJ_S * 4 + 16 * XI_S * 4);
    unsigned short* WoTl = WoTh + 16 * WO_S;                       // [16][264] each

    const int tid  = threadIdx.x;
    const int w    = tid >> 5;
    const int lane = tid & 31;
    const int g    = lane >> 2;        // 0..7
    const int tg   = lane & 3;         // 0..3
    const int b    = blockIdx.z;
    const int i0   = blockIdx.y * 16;
    const int j0   = blockIdx.x * 128;

    // ---- stage Xj rows (xj = g_xij cols 256..511) ----
    {
        const int jl = tid >> 2;
        const int hq = (tid & 3) * 64;
        const float* src = &g_xij[(size_t)(b * L_ + j0 + jl) * NTOT_ + H_ + hq];
        float* dst = &Xj[jl * XJ_S + hq];
        #pragma unroll
        for (int q = 0; q < 16; q++)
            *(float4*)&dst[q * 4] = *(const float4*)&src[q * 4];
    }
    // ---- stage Xi rows (xi = cols 0..255) ----
    {
        const int il = tid >> 5;
        const int hq = (tid & 31) * 8;
        const float* src = &g_xij[(size_t)(b * L_ + i0 + il) * NTOT_ + hq];
        float* dst = &Xi[il * XI_S + hq];
        *(float4*)&dst[0] = *(const float4*)&src[0];
        *(float4*)&dst[4] = *(const float4*)&src[4];
    }
    // ---- stage Wo^T as bf16 hi/lo, zero-padded to N=16 ----
    {
        const int h  = tid >> 1;              // 0..255
        const int nb = (tid & 1) * 8;
        #pragma unroll
        for (int q = 0; q < 8; q++) {
            int n = nb + q;
            float f = (n < NB_) ? Wo[h * NB_ + n] : 0.0f;
            unsigned short wh = __bfloat16_as_ushort(__float2bfloat16(f));
            float whf = __uint_as_float(((u32)wh) << 16);
            unsigned short wl = __bfloat16_as_ushort(__float2bfloat16(f - whf));
            WoTh[n * WO_S + h] = wh;
            WoTl[n * WO_S + h] = wl;
        }
    }

    const float boA = bo[2 * tg];
    const float boB = bo[2 * tg + 1];
    const float bo8 = bo[8];
    const float bo9 = bo[9];

    __syncthreads();

    const float* xip = &Xi[w * XI_S];

    for (int s = 0; s < 8; s++) {          // j-chunk
        float acc0[4] = {0.f, 0.f, 0.f, 0.f};
        float acc1[4] = {0.f, 0.f, 0.f, 0.f};
        const int jr = s * 16 + g;
        const float* xjp0 = &Xj[jr * XJ_S];
        const float* xjp1 = &Xj[(jr + 8) * XJ_S];

        #pragma unroll 4
        for (int k0 = 0; k0 < H_; k0 += 16) {
            const int h0 = k0 + 2 * tg;
            const int h1 = h0 + 8;
            u64 xiA  = *(const u64*)&xip[h0];
            u64 xiB  = *(const u64*)&xip[h1];
            u64 xj00 = *(const u64*)&xjp0[h0];
            u64 xj01 = *(const u64*)&xjp0[h1];
            u64 xj10 = *(const u64*)&xjp1[h0];
            u64 xj11 = *(const u64*)&xjp1[h1];

            u32 ah[4], al[4];
            makeA(xiA, xj00, ah[0], al[0]);   // row g,   k-cols 2tg..
            makeA(xiA, xj10, ah[1], al[1]);   // row g+8
            makeA(xiB, xj01, ah[2], al[2]);   // row g,   +8
            makeA(xiB, xj11, ah[3], al[3]);   // row g+8, +8

            u32 bh0a = *(const u32*)&WoTh[g * WO_S + h0];
            u32 bh0b = *(const u32*)&WoTh[g * WO_S + h1];
            u32 bh1a = *(const u32*)&WoTh[(8 + g) * WO_S + h0];
            u32 bh1b = *(const u32*)&WoTh[(8 + g) * WO_S + h1];
            u32 bl0a = *(const u32*)&WoTl[g * WO_S + h0];
            u32 bl0b = *(const u32*)&WoTl[g * WO_S + h1];
            u32 bl1a = *(const u32*)&WoTl[(8 + g) * WO_S + h0];
            u32 bl1b = *(const u32*)&WoTl[(8 + g) * WO_S + h1];

            mma16816(acc0, ah, bh0a, bh0b);
            mma16816(acc0, al, bh0a, bh0b);
            mma16816(acc0, ah, bl0a, bl0b);
            mma16816(acc1, ah, bh1a, bh1b);
            mma16816(acc1, al, bh1a, bh1b);
            mma16816(acc1, ah, bl1a, bl1b);
        }

        // epilogue: C[g][2tg,2tg+1] = acc0[0..1]; C[g+8][...] = acc0[2..3];
        // acc1 covers n = 8+2tg (valid only for tg==0 -> n=8,9)
        const int iG = i0 + w;
        const int jA = j0 + s * 16 + g;
        size_t baseA = ((size_t)(b * L_ + iG) * L_ + jA) * NB_;
        size_t baseB = baseA + 8 * NB_;            // row g+8

        *(u64*)&out[baseA + 2 * tg] = pk2(acc0[0] + boA, acc0[1] + boB);
        *(u64*)&out[baseB + 2 * tg] = pk2(acc0[2] + boA, acc0[3] + boB);
        if (tg == 0) {
            *(u64*)&out[baseA + 8] = pk2(acc1[0] + bo8, acc1[1] + bo9);
            *(u64*)&out[baseB + 8] = pk2(acc1[2] + bo8, acc1[3] + bo9);
        }
    }
}

// ---------------------------------------------------------------------------
extern "C" void kernel_launch(void* const* d_in, const int* in_sizes, int n_in,
                              void* d_out, int out_size)
{
    const float* x  = (const float*)d_in[0];
    const float* Wi = (const float*)d_in[1];
    const float* bi = (const float*)d_in[2];
    const float* Wj = (const float*)d_in[3];
    const float* bj = (const float*)d_in[4];
    const float* Wo = (const float*)d_in[5];
    const float* bo = (const float*)d_in[6];
    float* out = (float*)d_out;

    const int pair_smem = 128 * XJ_S * 4 + 16 * XI_S * 4 + 2 * 16 * WO_S * 2;
    cudaFuncSetAttribute(pair_kernel,
                         cudaFuncAttributeMaxDynamicSharedMemorySize, pair_smem);

    proj_kernel<<<dim3(4, 6, SPLITK_), 256>>>(x, Wi, Wj);
    reduce_kernel<<<dim3(384), 256>>>(bi, bj);
    pair_kernel<<<dim3(L_ / 128, L_ / 16, B_), 512, pair_smem>>>(Wo, bo, out);
}

// round 13
// speedup vs baseline: 1.2942x; 1.0053x over previous
#include <cuda_runtime.h>
#include <cuda_bf16.h>
#include <cstdint>

// ---------------------------------------------------------------------------
// DistancePredictor: out[b,i,j,n] = relu(xi[b,i,:]*xj[b,j,:]) @ Wo[:,n] + bo[n]
//   xi = x@Wi + bi, xj = x@Wj + bj
// B=2, L=384, D=1280, H=256, NB=10
// ---------------------------------------------------------------------------

#define B_    2
#define L_    384
#define D_    1280
#define H_    256
#define NB_   10
#define ROWS_ 768
#define NTOT_ 512              // concat: cols 0-255 = xi, 256-511 = xj
#define SPLITK_ 12             // over eff-K = 3*1280 = 3840

__device__ __align__(16) float g_xij[ROWS_ * NTOT_];
__device__ __align__(16) float g_part[SPLITK_ * ROWS_ * NTOT_];
// double-bf16 decompositions
__device__ __align__(16) __nv_bfloat16 g_xh [ROWS_ * D_];
__device__ __align__(16) __nv_bfloat16 g_xl [ROWS_ * D_];
__device__ __align__(16) __nv_bfloat16 g_wth[NTOT_ * D_];   // W^T hi  [n][k]
__device__ __align__(16) __nv_bfloat16 g_wtl[NTOT_ * D_];   // W^T lo

typedef unsigned long long u64;
typedef unsigned int       u32;
typedef unsigned short     u16;

__device__ __forceinline__ u64 pk2(float a, float b) {
    u64 r;
    asm("mov.b64 %0, {%1, %2};"
        : "=l"(r) : "r"(__float_as_uint(a)), "r"(__float_as_uint(b)));
    return r;
}
__device__ __forceinline__ u64 mul2(u64 a, u64 b) {
    u64 d;
    asm("mul.rn.f32x2 %0, %1, %2;" : "=l"(d) : "l"(a), "l"(b));
    return d;
}
__device__ __forceinline__ void cp16(u32 s, const void* g) {
    asm volatile("cp.async.cg.shared.global [%0], [%1], 16;\n" :: "r"(s), "l"(g));
}
__device__ __forceinline__ void cp_commit() {
    asm volatile("cp.async.commit_group;\n" ::: "memory");
}
__device__ __forceinline__ void mma16816(float* d, const u32* a, u32 b0, u32 b1) {
    asm volatile(
        "mma.sync.aligned.m16n8k16.row.col.f32.bf16.bf16.f32 "
        "{%0,%1,%2,%3}, {%4,%5,%6,%7}, {%8,%9}, {%0,%1,%2,%3};"
        : "+f"(d[0]), "+f"(d[1]), "+f"(d[2]), "+f"(d[3])
        : "r"(a[0]), "r"(a[1]), "r"(a[2]), "r"(a[3]), "r"(b0), "r"(b1));
}

// ---------------------------------------------------------------------------
// Stage 0: build bf16 hi/lo copies of X and [Wi|Wj]^T
// grid 1280 x 256: blocks 0..959 -> X (4 floats/thread), 960.. -> W^T
// ---------------------------------------------------------------------------
__global__ __launch_bounds__(256) void convert_kernel(
    const float* __restrict__ x,
    const float* __restrict__ Wi, const float* __restrict__ Wj)
{
    const int t = blockIdx.x * 256 + threadIdx.x;
    if (blockIdx.x < 960) {
        const int q = t * 4;                    // < 983040
        float4 v = *(const float4*)&x[q];
        u16 h[4], l[4];
        float f[4] = {v.x, v.y, v.z, v.w};
        #pragma unroll
        for (int p = 0; p < 4; p++) {
            __nv_bfloat16 hb = __float2bfloat16_rn(f[p]);
            h[p] = __bfloat16_as_ushort(hb);
            l[p] = __bfloat16_as_ushort(
                __float2bfloat16_rn(f[p] - __bfloat162float(hb)));
        }
        *(u64*)&g_xh[q] = *(const u64*)h;
        *(u64*)&g_xl[q] = *(const u64*)l;
    } else {
        const int t2 = t - 960 * 256;           // 0..81919
        const int n  = t2 / 160;                // 0..511
        const int k0 = (t2 % 160) * 8;
        const float* src = (n < H_) ? &Wi[n] : &Wj[n - H_];
        u16 h[8], l[8];
        #pragma unroll
        for (int p = 0; p < 8; p++) {
            float f = src[(size_t)(k0 + p) * H_];
            __nv_bfloat16 hb = __float2bfloat16_rn(f);
            h[p] = __bfloat16_as_ushort(hb);
            l[p] = __bfloat16_as_ushort(
                __float2bfloat16_rn(f - __bfloat162float(hb)));
        }
        *(uint4*)&g_wth[(size_t)n * D_ + k0] = *(const uint4*)h;
        *(uint4*)&g_wtl[(size_t)n * D_ + k0] = *(const uint4*)l;
    }
}

// ---------------------------------------------------------------------------
// Stage 1: tensorized projection GEMM.  C[768,512] = X @ [Wi|Wj], computed as
//   Xh@Wh + Xl@Wh + Xh@Wl  == one bf16 GEMM with eff-K = 3840 (phase-mapped).
// 128x128 tile, 256 thr (8 warps, 2x4 -> m64n32/warp), BK=32 bf16,
// 3-stage cp.async. grid (4, 6, 12); split s covers eff-chunks s*10..s*10+9.
// ---------------------------------------------------------------------------
#define AS_K 40                 // bf16 row stride: conflict-free u32 frags

__global__ __launch_bounds__(256, 2) void proj_mma()
{
    extern __shared__ __align__(16) __nv_bfloat16 smem[];
    __nv_bfloat16* As = smem;                    // [3][128*AS_K]
    __nv_bfloat16* Bs = smem + 3 * 128 * AS_K;   // [3][128*AS_K]

    const int split = blockIdx.z;
    const int m0    = blockIdx.y * 128;
    const int n0    = blockIdx.x * 128;
    float* P = g_part + (size_t)split * ROWS_ * NTOT_;

    const int tid  = threadIdx.x;
    const int w    = tid >> 5;
    const int lane = tid & 31;
    const int wm   = w & 1;          // m-half (64)
    const int wn   = w >> 1;         // n-quarter (32)
    const int g    = lane >> 2;
    const int tg   = lane & 3;

    const int row  = tid >> 1;       // 0..127 (loader row, both A and B)
    const int half = tid & 1;        // 16-bf16 half

    float acc[4][4][4];
    #pragma unroll
    for (int mf = 0; mf < 4; mf++)
        #pragma unroll
        for (int nf = 0; nf < 4; nf++)
            #pragma unroll
            for (int c = 0; c < 4; c++) acc[mf][nf][c] = 0.0f;

    auto issue = [&](int c, int s) {
        const int cg    = split * 10 + c;      // global eff-chunk
        const int phase = cg / 40;             // 0:h*h 1:l*h 2:h*l
        const int k0    = (cg % 40) * 32;
        const __nv_bfloat16* Asrc = (phase == 1) ? g_xl  : g_xh;
        const __nv_bfloat16* Bsrc = (phase == 2) ? g_wtl : g_wth;

        const __nv_bfloat16* ga = &Asrc[(size_t)(m0 + row) * D_ + k0 + half * 16];
        u32 sa = (u32)__cvta_generic_to_shared(&As[s * 128 * AS_K + row * AS_K + half * 16]);
        cp16(sa,      ga);
        cp16(sa + 16, ga + 8);
        const __nv_bfloat16* gb = &Bsrc[(size_t)(n0 + row) * D_ + k0 + half * 16];
        u32 sb = (u32)__cvta_generic_to_shared(&Bs[s * 128 * AS_K + row * AS_K + half * 16]);
        cp16(sb,      gb);
        cp16(sb + 16, gb + 8);
        cp_commit();
    };

    issue(0, 0);
    issue(1, 1);

    for (int c = 0; c < 10; c++) {
        if (c < 9) asm volatile("cp.async.wait_group 1;\n" ::: "memory");
        else       asm volatile("cp.async.wait_group 0;\n" ::: "memory");
        __syncthreads();

        const __nv_bfloat16* A = &As[(c % 3) * 128 * AS_K];
        const __nv_bfloat16* Bl = &Bs[(c % 3) * 128 * AS_K];

        #pragma unroll
        for (int kk = 0; kk < 32; kk += 16) {
            u32 a[4][4];
            #pragma unroll
            for (int mf = 0; mf < 4; mf++) {
                const int r0 = wm * 64 + mf * 16 + g;
                a[mf][0] = *(const u32*)&A[(r0    ) * AS_K + kk + 2 * tg];
                a[mf][1] = *(const u32*)&A[(r0 + 8) * AS_K + kk + 2 * tg];
                a[mf][2] = *(const u32*)&A[(r0    ) * AS_K + kk + 2 * tg + 8];
                a[mf][3] = *(const u32*)&A[(r0 + 8) * AS_K + kk + 2 * tg + 8];
            }
            u32 b[4][2];
            #pragma unroll
            for (int nf = 0; nf < 4; nf++) {
                const int nr = wn * 32 + nf * 8 + g;
                b[nf][0] = *(const u32*)&Bl[nr * AS_K + kk + 2 * tg];
                b[nf][1] = *(const u32*)&Bl[nr * AS_K + kk + 2 * tg + 8];
            }
            #pragma unroll
            for (int mf = 0; mf < 4; mf++)
                #pragma unroll
                for (int nf = 0; nf < 4; nf++)
                    mma16816(acc[mf][nf], a[mf], b[nf][0], b[nf][1]);
        }
        if (c + 2 < 10) issue(c + 2, (c + 2) % 3);
    }

    // epilogue: scatter fp32 partials
    #pragma unroll
    for (int mf = 0; mf < 4; mf++) {
        const int m = m0 + wm * 64 + mf * 16;
        #pragma unroll
        for (int nf = 0; nf < 4; nf++) {
            const int n = n0 + wn * 32 + nf * 8 + 2 * tg;
            *(u64*)&P[(size_t)(m + g    ) * NTOT_ + n] = pk2(acc[mf][nf][0], acc[mf][nf][1]);
            *(u64*)&P[(size_t)(m + g + 8) * NTOT_ + n] = pk2(acc[mf][nf][2], acc[mf][nf][3]);
        }
    }
}

// ---------------------------------------------------------------------------
// Stage 1b: sum 12 split-K partials + bias -> g_xij  (grid 384 x 256)
// ---------------------------------------------------------------------------
__global__ __launch_bounds__(256) void reduce_kernel(
    const float* __restrict__ bi, const float* __restrict__ bj)
{
    const int q    = blockIdx.x * 256 + threadIdx.x;
    const int flat = q << 2;
    const int col  = flat & (NTOT_ - 1);

    float4 s = *(const float4*)&g_part[flat];
    #pragma unroll
    for (int sp = 1; sp < SPLITK_; sp++) {
        float4 v = *(const float4*)&g_part[(size_t)sp * ROWS_ * NTOT_ + flat];
        s.x += v.x; s.y += v.y; s.z += v.z; s.w += v.w;
    }
    const float* bias = (col < H_) ? (bi + col) : (bj + col - H_);
    float4 bv = *(const float4*)bias;
    s.x += bv.x; s.y += bv.y; s.z += bv.z; s.w += bv.w;

    *(float4*)&g_xij[flat] = s;
}

// ---------------------------------------------------------------------------
// Stage 2 (unchanged from R11): tensorized pair stage.
// ---------------------------------------------------------------------------
#define XJ_S 260
#define XI_S 260
#define WO_S 264

__device__ __forceinline__ void makeA(u64 xi2, u64 xj2, u32& rh, u32& rl) {
    u64 p = mul2(xi2, xj2);
    float plo = fmaxf(__uint_as_float((u32)p), 0.0f);
    float phi = fmaxf(__uint_as_float((u32)(p >> 32)), 0.0f);
    asm("cvt.rn.bf16x2.f32 %0, %1, %2;" : "=r"(rh) : "f"(phi), "f"(plo));
    float qlo = plo - __uint_as_float(rh << 16);
    float qhi = phi - __uint_as_float(rh & 0xffff0000u);
    asm("cvt.rn.bf16x2.f32 %0, %1, %2;" : "=r"(rl) : "f"(qhi), "f"(qlo));
}

__global__ __launch_bounds__(512) void pair_kernel(
    const float* __restrict__ Wo, const float* __restrict__ bo,
    float* __restrict__ out)
{
    extern __shared__ __align__(16) char smraw[];
    float* Xj = (float*)smraw;                                   // [128][260]
    float* Xi = (float*)(smraw + 128 * XJ_S * 4);                // [16][260]
    u16*  WoTh = (u16*)(smraw + 128 * XJ_S * 4 + 16 * XI_S * 4);
    u16*  WoTl = WoTh + 16 * WO_S;

    const int tid  = threadIdx.x;
    const int w    = tid >> 5;
    const int lane = tid & 31;
    const int g    = lane >> 2;
    const int tg   = lane & 3;
    const int b    = blockIdx.z;
    const int i0   = blockIdx.y * 16;
    const int j0   = blockIdx.x * 128;

    {
        const int jl = tid >> 2;
        const int hq = (tid & 3) * 64;
        const float* src = &g_xij[(size_t)(b * L_ + j0 + jl) * NTOT_ + H_ + hq];
        float* dst = &Xj[jl * XJ_S + hq];
        #pragma unroll
        for (int q = 0; q < 16; q++)
            *(float4*)&dst[q * 4] = *(const float4*)&src[q * 4];
    }
    {
        const int il = tid >> 5;
        const int hq = (tid & 31) * 8;
        const float* src = &g_xij[(size_t)(b * L_ + i0 + il) * NTOT_ + hq];
        float* dst = &Xi[il * XI_S + hq];
        *(float4*)&dst[0] = *(const float4*)&src[0];
        *(float4*)&dst[4] = *(const float4*)&src[4];
    }
    {
        const int h  = tid >> 1;
        const int nb = (tid & 1) * 8;
        #pragma unroll
        for (int q = 0; q < 8; q++) {
            int n = nb + q;
            float f = (n < NB_) ? Wo[h * NB_ + n] : 0.0f;
            u16 wh = __bfloat16_as_ushort(__float2bfloat16(f));
            float whf = __uint_as_float(((u32)wh) << 16);
            u16 wl = __bfloat16_as_ushort(__float2bfloat16(f - whf));
            WoTh[n * WO_S + h] = wh;
            WoTl[n * WO_S + h] = wl;
        }
    }

    const float boA = bo[2 * tg];
    const float boB = bo[2 * tg + 1];
    const float bo8 = bo[8];
    const float bo9 = bo[9];

    __syncthreads();

    const float* xip = &Xi[w * XI_S];

    for (int s = 0; s < 8; s++) {
        float acc0[4] = {0.f, 0.f, 0.f, 0.f};
        float acc1[4] = {0.f, 0.f, 0.f, 0.f};
        const int jr = s * 16 + g;
        const float* xjp0 = &Xj[jr * XJ_S];
        const float* xjp1 = &Xj[(jr + 8) * XJ_S];

        #pragma unroll 4
        for (int k0 = 0; k0 < H_; k0 += 16) {
            const int h0 = k0 + 2 * tg;
            const int h1 = h0 + 8;
            u64 xiA  = *(const u64*)&xip[h0];
            u64 xiB  = *(const u64*)&xip[h1];
            u64 xj00 = *(const u64*)&xjp0[h0];
            u64 xj01 = *(const u64*)&xjp0[h1];
            u64 xj10 = *(const u64*)&xjp1[h0];
            u64 xj11 = *(const u64*)&xjp1[h1];

            u32 ah[4], al[4];
            makeA(xiA, xj00, ah[0], al[0]);
            makeA(xiA, xj10, ah[1], al[1]);
            makeA(xiB, xj01, ah[2], al[2]);
            makeA(xiB, xj11, ah[3], al[3]);

            u32 bh0a = *(const u32*)&WoTh[g * WO_S + h0];
            u32 bh0b = *(const u32*)&WoTh[g * WO_S + h1];
            u32 bh1a = *(const u32*)&WoTh[(8 + g) * WO_S + h0];
            u32 bh1b = *(const u32*)&WoTh[(8 + g) * WO_S + h1];
            u32 bl0a = *(const u32*)&WoTl[g * WO_S + h0];
            u32 bl0b = *(const u32*)&WoTl[g * WO_S + h1];
            u32 bl1a = *(const u32*)&WoTl[(8 + g) * WO_S + h0];
            u32 bl1b = *(const u32*)&WoTl[(8 + g) * WO_S + h1];

            mma16816(acc0, ah, bh0a, bh0b);
            mma16816(acc0, al, bh0a, bh0b);
            mma16816(acc0, ah, bl0a, bl0b);
            mma16816(acc1, ah, bh1a, bh1b);
            mma16816(acc1, al, bh1a, bh1b);
            mma16816(acc1, ah, bl1a, bl1b);
        }

        const int iG = i0 + w;
        const int jA = j0 + s * 16 + g;
        size_t baseA = ((size_t)(b * L_ + iG) * L_ + jA) * NB_;
        size_t baseB = baseA + 8 * NB_;

        *(u64*)&out[baseA + 2 * tg] = pk2(acc0[0] + boA, acc0[1] + boB);
        *(u64*)&out[baseB + 2 * tg] = pk2(acc0[2] + boA, acc0[3] + boB);
        if (tg == 0) {
            *(u64*)&out[baseA + 8] = pk2(acc1[0] + bo8, acc1[1] + bo9);
            *(u64*)&out[baseB + 8] = pk2(acc1[2] + bo8, acc1[3] + bo9);
        }
    }
}

// ---------------------------------------------------------------------------
extern "C" void kernel_launch(void* const* d_in, const int* in_sizes, int n_in,
                              void* d_out, int out_size)
{
    const float* x  = (const float*)d_in[0];
    const float* Wi = (const float*)d_in[1];
    const float* bi = (const float*)d_in[2];
    const float* Wj = (const float*)d_in[3];
    const float* bj = (const float*)d_in[4];
    const float* Wo = (const float*)d_in[5];
    const float* bo = (const float*)d_in[6];
    float* out = (float*)d_out;

    const int proj_smem = 2 * 3 * 128 * AS_K * 2;    // 61,440 B
    cudaFuncSetAttribute(proj_mma,
                         cudaFuncAttributeMaxDynamicSharedMemorySize, proj_smem);
    const int pair_smem = 128 * XJ_S * 4 + 16 * XI_S * 4 + 2 * 16 * WO_S * 2;
    cudaFuncSetAttribute(pair_kernel,
                         cudaFuncAttributeMaxDynamicSharedMemorySize, pair_smem);

    convert_kernel<<<1280, 256>>>(x, Wi, Wj);
    proj_mma<<<dim3(4, 6, SPLITK_), 256, proj_smem>>>();
    reduce_kernel<<<384, 256>>>(bi, bj);
    pair_kernel<<<dim3(L_ / 128, L_ / 16, B_), 512, pair_smem>>>(Wo, bo, out);
}

// round 17
// speedup vs baseline: 1.4017x; 1.0831x over previous
#include <cuda_runtime.h>
#include <cuda_bf16.h>
#include <cstdint>

// ---------------------------------------------------------------------------
// DistancePredictor: out[b,i,j,n] = relu(xi[b,i,:]*xj[b,j,:]) @ Wo[:,n] + bo[n]
//   xi = x@Wi + bi, xj = x@Wj + bj
// B=2, L=384, D=1280, H=256, NB=10
// ---------------------------------------------------------------------------

#define B_    2
#define L_    384
#define D_    1280
#define H_    256
#define NB_   10
#define ROWS_ 768
#define NTOT_ 512              // concat: cols 0-255 = xi, 256-511 = xj
#define SPLITK_ 12             // over eff-K = 3*1280 = 3840

__device__ __align__(16) float g_xij[ROWS_ * NTOT_];
__device__ __align__(16) float g_part[SPLITK_ * ROWS_ * NTOT_];
// double-bf16 decompositions
__device__ __align__(16) __nv_bfloat16 g_xh [ROWS_ * D_];
__device__ __align__(16) __nv_bfloat16 g_xl [ROWS_ * D_];
__device__ __align__(16) __nv_bfloat16 g_wth[NTOT_ * D_];   // W^T hi  [n][k]
__device__ __align__(16) __nv_bfloat16 g_wtl[NTOT_ * D_];   // W^T lo

typedef unsigned long long u64;
typedef unsigned int       u32;
typedef unsigned short     u16;

__device__ __forceinline__ u64 pk2(float a, float b) {
    u64 r;
    asm("mov.b64 %0, {%1, %2};"
        : "=l"(r) : "r"(__float_as_uint(a)), "r"(__float_as_uint(b)));
    return r;
}
__device__ __forceinline__ u64 mul2(u64 a, u64 b) {
    u64 d;
    asm("mul.rn.f32x2 %0, %1, %2;" : "=l"(d) : "l"(a), "l"(b));
    return d;
}
__device__ __forceinline__ void cp16(u32 s, const void* g) {
    asm volatile("cp.async.cg.shared.global [%0], [%1], 16;\n" :: "r"(s), "l"(g));
}
__device__ __forceinline__ void cp_commit() {
    asm volatile("cp.async.commit_group;\n" ::: "memory");
}
__device__ __forceinline__ void mma16816(float* d, const u32* a, u32 b0, u32 b1) {
    asm volatile(
        "mma.sync.aligned.m16n8k16.row.col.f32.bf16.bf16.f32 "
        "{%0,%1,%2,%3}, {%4,%5,%6,%7}, {%8,%9}, {%0,%1,%2,%3};"
        : "+f"(d[0]), "+f"(d[1]), "+f"(d[2]), "+f"(d[3])
        : "r"(a[0]), "r"(a[1]), "r"(a[2]), "r"(a[3]), "r"(b0), "r"(b1));
}

// ---------------------------------------------------------------------------
// Stage 0: build bf16 hi/lo copies of X and [Wi|Wj]^T
// ---------------------------------------------------------------------------
__global__ __launch_bounds__(256) void convert_kernel(
    const float* __restrict__ x,
    const float* __restrict__ Wi, const float* __restrict__ Wj)
{
    const int t = blockIdx.x * 256 + threadIdx.x;
    if (blockIdx.x < 960) {
        const int q = t * 4;
        float4 v = *(const float4*)&x[q];
        u16 h[4], l[4];
        float f[4] = {v.x, v.y, v.z, v.w};
        #pragma unroll
        for (int p = 0; p < 4; p++) {
            __nv_bfloat16 hb = __float2bfloat16_rn(f[p]);
            h[p] = __bfloat16_as_ushort(hb);
            l[p] = __bfloat16_as_ushort(
                __float2bfloat16_rn(f[p] - __bfloat162float(hb)));
        }
        *(u64*)&g_xh[q] = *(const u64*)h;
        *(u64*)&g_xl[q] = *(const u64*)l;
    } else {
        const int t2 = t - 960 * 256;
        const int n  = t2 / 160;
        const int k0 = (t2 % 160) * 8;
        const float* src = (n < H_) ? &Wi[n] : &Wj[n - H_];
        u16 h[8], l[8];
        #pragma unroll
        for (int p = 0; p < 8; p++) {
            float f = src[(size_t)(k0 + p) * H_];
            __nv_bfloat16 hb = __float2bfloat16_rn(f);
            h[p] = __bfloat16_as_ushort(hb);
            l[p] = __bfloat16_as_ushort(
                __float2bfloat16_rn(f - __bfloat162float(hb)));
        }
        *(uint4*)&g_wth[(size_t)n * D_ + k0] = *(const uint4*)h;
        *(uint4*)&g_wtl[(size_t)n * D_ + k0] = *(const uint4*)l;
    }
}

// ---------------------------------------------------------------------------
// Stage 1: tensorized projection GEMM (unchanged from R13).
// ---------------------------------------------------------------------------
#define AS_K 40

__global__ __launch_bounds__(256, 2) void proj_mma()
{
    extern __shared__ __align__(16) __nv_bfloat16 smem[];
    __nv_bfloat16* As = smem;
    __nv_bfloat16* Bs = smem + 3 * 128 * AS_K;

    const int split = blockIdx.z;
    const int m0    = blockIdx.y * 128;
    const int n0    = blockIdx.x * 128;
    float* P = g_part + (size_t)split * ROWS_ * NTOT_;

    const int tid  = threadIdx.x;
    const int w    = tid >> 5;
    const int lane = tid & 31;
    const int wm   = w & 1;
    const int wn   = w >> 1;
    const int g    = lane >> 2;
    const int tg   = lane & 3;

    const int row  = tid >> 1;
    const int half = tid & 1;

    float acc[4][4][4];
    #pragma unroll
    for (int mf = 0; mf < 4; mf++)
        #pragma unroll
        for (int nf = 0; nf < 4; nf++)
            #pragma unroll
            for (int c = 0; c < 4; c++) acc[mf][nf][c] = 0.0f;

    auto issue = [&](int c, int s) {
        const int cg    = split * 10 + c;
        const int phase = cg / 40;
        const int k0    = (cg % 40) * 32;
        const __nv_bfloat16* Asrc = (phase == 1) ? g_xl  : g_xh;
        const __nv_bfloat16* Bsrc = (phase == 2) ? g_wtl : g_wth;

        const __nv_bfloat16* ga = &Asrc[(size_t)(m0 + row) * D_ + k0 + half * 16];
        u32 sa = (u32)__cvta_generic_to_shared(&As[s * 128 * AS_K + row * AS_K + half * 16]);
        cp16(sa,      ga);
        cp16(sa + 16, ga + 8);
        const __nv_bfloat16* gb = &Bsrc[(size_t)(n0 + row) * D_ + k0 + half * 16];
        u32 sb = (u32)__cvta_generic_to_shared(&Bs[s * 128 * AS_K + row * AS_K + half * 16]);
        cp16(sb,      gb);
        cp16(sb + 16, gb + 8);
        cp_commit();
    };

    issue(0, 0);
    issue(1, 1);

    for (int c = 0; c < 10; c++) {
        if (c < 9) asm volatile("cp.async.wait_group 1;\n" ::: "memory");
        else       asm volatile("cp.async.wait_group 0;\n" ::: "memory");
        __syncthreads();

        const __nv_bfloat16* A  = &As[(c % 3) * 128 * AS_K];
        const __nv_bfloat16* Bl = &Bs[(c % 3) * 128 * AS_K];

        #pragma unroll
        for (int kk = 0; kk < 32; kk += 16) {
            u32 a[4][4];
            #pragma unroll
            for (int mf = 0; mf < 4; mf++) {
                const int r0 = wm * 64 + mf * 16 + g;
                a[mf][0] = *(const u32*)&A[(r0    ) * AS_K + kk + 2 * tg];
                a[mf][1] = *(const u32*)&A[(r0 + 8) * AS_K + kk + 2 * tg];
                a[mf][2] = *(const u32*)&A[(r0    ) * AS_K + kk + 2 * tg + 8];
                a[mf][3] = *(const u32*)&A[(r0 + 8) * AS_K + kk + 2 * tg + 8];
            }
            u32 b[4][2];
            #pragma unroll
            for (int nf = 0; nf < 4; nf++) {
                const int nr = wn * 32 + nf * 8 + g;
                b[nf][0] = *(const u32*)&Bl[nr * AS_K + kk + 2 * tg];
                b[nf][1] = *(const u32*)&Bl[nr * AS_K + kk + 2 * tg + 8];
            }
            #pragma unroll
            for (int mf = 0; mf < 4; mf++)
                #pragma unroll
                for (int nf = 0; nf < 4; nf++)
                    mma16816(acc[mf][nf], a[mf], b[nf][0], b[nf][1]);
        }
        if (c + 2 < 10) issue(c + 2, (c + 2) % 3);
    }

    #pragma unroll
    for (int mf = 0; mf < 4; mf++) {
        const int m = m0 + wm * 64 + mf * 16;
        #pragma unroll
        for (int nf = 0; nf < 4; nf++) {
            const int n = n0 + wn * 32 + nf * 8 + 2 * tg;
            *(u64*)&P[(size_t)(m + g    ) * NTOT_ + n] = pk2(acc[mf][nf][0], acc[mf][nf][1]);
            *(u64*)&P[(size_t)(m + g + 8) * NTOT_ + n] = pk2(acc[mf][nf][2], acc[mf][nf][3]);
        }
    }
}

// ---------------------------------------------------------------------------
// Stage 1b: sum 12 split-K partials + bias -> g_xij
// ---------------------------------------------------------------------------
__global__ __launch_bounds__(256) void reduce_kernel(
    const float* __restrict__ bi, const float* __restrict__ bj)
{
    const int q    = blockIdx.x * 256 + threadIdx.x;
    const int flat = q << 2;
    const int col  = flat & (NTOT_ - 1);

    float4 s = *(const float4*)&g_part[flat];
    #pragma unroll
    for (int sp = 1; sp < SPLITK_; sp++) {
        float4 v = *(const float4*)&g_part[(size_t)sp * ROWS_ * NTOT_ + flat];
        s.x += v.x; s.y += v.y; s.z += v.z; s.w += v.w;
    }
    const float* bias = (col < H_) ? (bi + col) : (bj + col - H_);
    float4 bv = *(const float4*)bias;
    s.x += bv.x; s.y += bv.y; s.z += bv.z; s.w += bv.w;

    *(float4*)&g_xij[flat] = s;
}

// ---------------------------------------------------------------------------
// Stage 2: tensorized pair stage, k-OUTER loop order.
// Per k16-step: load xi + 8 Wo frags ONCE, sweep 8 j-chunks (xj + makeA + MMA).
// Accumulators for all 8 chunks live in registers (64 floats).
// ---------------------------------------------------------------------------
#define XJ_S 260
#define XI_S 260
#define WO_S 264

__device__ __forceinline__ void makeA(u64 xi2, u64 xj2, u32& rh, u32& rl) {
    u64 p = mul2(xi2, xj2);
    float plo = fmaxf(__uint_as_float((u32)p), 0.0f);
    float phi = fmaxf(__uint_as_float((u32)(p >> 32)), 0.0f);
    asm("cvt.rn.bf16x2.f32 %0, %1, %2;" : "=r"(rh) : "f"(phi), "f"(plo));
    float qlo = plo - __uint_as_float(rh << 16);
    float qhi = phi - __uint_as_float(rh & 0xffff0000u);
    asm("cvt.rn.bf16x2.f32 %0, %1, %2;" : "=r"(rl) : "f"(qhi), "f"(qlo));
}

__global__ __launch_bounds__(512) void pair_kernel(
    const float* __restrict__ Wo, const float* __restrict__ bo,
    float* __restrict__ out)
{
    extern __shared__ __align__(16) char smraw[];
    float* Xj = (float*)smraw;                                   // [128][260]
    float* Xi = (float*)(smraw + 128 * XJ_S * 4);                // [16][260]
    u16*  WoTh = (u16*)(smraw + 128 * XJ_S * 4 + 16 * XI_S * 4);
    u16*  WoTl = WoTh + 16 * WO_S;

    const int tid  = threadIdx.x;
    const int w    = tid >> 5;
    const int lane = tid & 31;
    const int g    = lane >> 2;
    const int tg   = lane & 3;
    const int b    = blockIdx.z;
    const int i0   = blockIdx.y * 16;
    const int j0   = blockIdx.x * 128;

    {
        const int jl = tid >> 2;
        const int hq = (tid & 3) * 64;
        const float* src = &g_xij[(size_t)(b * L_ + j0 + jl) * NTOT_ + H_ + hq];
        float* dst = &Xj[jl * XJ_S + hq];
        #pragma unroll
        for (int q = 0; q < 16; q++)
            *(float4*)&dst[q * 4] = *(const float4*)&src[q * 4];
    }
    {
        const int il = tid >> 5;
        const int hq = (tid & 31) * 8;
        const float* src = &g_xij[(size_t)(b * L_ + i0 + il) * NTOT_ + hq];
        float* dst = &Xi[il * XI_S + hq];
        *(float4*)&dst[0] = *(const float4*)&src[0];
        *(float4*)&dst[4] = *(const float4*)&src[4];
    }
    {
        const int h  = tid >> 1;
        const int nb = (tid & 1) * 8;
        #pragma unroll
        for (int q = 0; q < 8; q++) {
            int n = nb + q;
            float f = (n < NB_) ? Wo[h * NB_ + n] : 0.0f;
            u16 wh = __bfloat16_as_ushort(__float2bfloat16(f));
            float whf = __uint_as_float(((u32)wh) << 16);
            u16 wl = __bfloat16_as_ushort(__float2bfloat16(f - whf));
            WoTh[n * WO_S + h] = wh;
            WoTl[n * WO_S + h] = wl;
        }
    }

    const float boA = bo[2 * tg];
    const float boB = bo[2 * tg + 1];
    const float bo8 = bo[8];
    const float bo9 = bo[9];

    __syncthreads();

    const float* xip = &Xi[w * XI_S];

    // acc[s][0..3] = n 0-7 block (acc0), acc[s][4..7] = n 8-15 block (acc1)
    float acc[8][8];
    #pragma unroll
    for (int s = 0; s < 8; s++)
        #pragma unroll
        for (int c = 0; c < 8; c++) acc[s][c] = 0.0f;

    #pragma unroll 2
    for (int k0 = 0; k0 < H_; k0 += 16) {
        const int h0 = k0 + 2 * tg;
        const int h1 = h0 + 8;

        // invariant across j-chunks: xi pair + all 8 Wo fragments
        u64 xiA = *(const u64*)&xip[h0];
        u64 xiB = *(const u64*)&xip[h1];

        u32 bh0a = *(const u32*)&WoTh[g * WO_S + h0];
        u32 bh0b = *(const u32*)&WoTh[g * WO_S + h1];
        u32 bh1a = *(const u32*)&WoTh[(8 + g) * WO_S + h0];
        u32 bh1b = *(const u32*)&WoTh[(8 + g) * WO_S + h1];
        u32 bl0a = *(const u32*)&WoTl[g * WO_S + h0];
        u32 bl0b = *(const u32*)&WoTl[g * WO_S + h1];
        u32 bl1a = *(const u32*)&WoTl[(8 + g) * WO_S + h0];
        u32 bl1b = *(const u32*)&WoTl[(8 + g) * WO_S + h1];

        #pragma unroll
        for (int s = 0; s < 8; s++) {
            const int jr = s * 16 + g;
            const float* xjp0 = &Xj[jr * XJ_S];
            const float* xjp1 = &Xj[(jr + 8) * XJ_S];
            u64 xj00 = *(const u64*)&xjp0[h0];
            u64 xj01 = *(const u64*)&xjp0[h1];
            u64 xj10 = *(const u64*)&xjp1[h0];
            u64 xj11 = *(const u64*)&xjp1[h1];

            u32 ah[4], al[4];
            makeA(xiA, xj00, ah[0], al[0]);
            makeA(xiA, xj10, ah[1], al[1]);
            makeA(xiB, xj01, ah[2], al[2]);
            makeA(xiB, xj11, ah[3], al[3]);

            mma16816(&acc[s][0], ah, bh0a, bh0b);
            mma16816(&acc[s][0], al, bh0a, bh0b);
            mma16816(&acc[s][0], ah, bl0a, bl0b);
            mma16816(&acc[s][4], ah, bh1a, bh1b);
            mma16816(&acc[s][4], al, bh1a, bh1b);
            mma16816(&acc[s][4], ah, bl1a, bl1b);
        }
    }

    // ---- epilogue ----
    const int iG = i0 + w;
    #pragma unroll
    for (int s = 0; s < 8; s++) {
        const int jA = j0 + s * 16 + g;
        size_t baseA = ((size_t)(b * L_ + iG) * L_ + jA) * NB_;
        size_t baseB = baseA + 8 * NB_;

        *(u64*)&out[baseA + 2 * tg] = pk2(acc[s][0] + boA, acc[s][1] + boB);
        *(u64*)&out[baseB + 2 * tg] = pk2(acc[s][2] + boA, acc[s][3] + boB);
        if (tg == 0) {
            *(u64*)&out[baseA + 8] = pk2(acc[s][4] + bo8, acc[s][5] + bo9);
            *(u64*)&out[baseB + 8] = pk2(acc[s][6] + bo8, acc[s][7] + bo9);
        }
    }
}

// ---------------------------------------------------------------------------
extern "C" void kernel_launch(void* const* d_in, const int* in_sizes, int n_in,
                              void* d_out, int out_size)
{
    const float* x  = (const float*)d_in[0];
    const float* Wi = (const float*)d_in[1];
    const float* bi = (const float*)d_in[2];
    const float* Wj = (const float*)d_in[3];
    const float* bj = (const float*)d_in[4];
    const float* Wo = (const float*)d_in[5];
    const float* bo = (const float*)d_in[6];
    float* out = (float*)d_out;

    const int proj_smem = 2 * 3 * 128 * AS_K * 2;
    cudaFuncSetAttribute(proj_mma,
                         cudaFuncAttributeMaxDynamicSharedMemorySize, proj_smem);
    const int pair_smem = 128 * XJ_S * 4 + 16 * XI_S * 4 + 2 * 16 * WO_S * 2;
    cudaFuncSetAttribute(pair_kernel,
                         cudaFuncAttributeMaxDynamicSharedMemorySize, pair_smem);

    convert_kernel<<<1280, 256>>>(x, Wi, Wj);
    proj_mma<<<dim3(4, 6, SPLITK_), 256, proj_smem>>>();
    reduce_kernel<<<384, 256>>>(bi, bj);
    pair_kernel<<<dim3(L_ / 128, L_ / 16, B_), 512, pair_smem>>>(Wo, bo, out);
}